// round 3
// baseline (speedup 1.0000x reference)
#include <cuda_runtime.h>
#include <math.h>

// ---------------- problem constants ----------------
#define N_USER   50000
#define N_MOVIE  20000
#define N_REVIEW 200000
#define N_TOTAL  270000
#define IN_CH    768
#define HIDC     256
#define OUT_CH   128
#define NHEAD    8
#define DHEAD    32
#define NEDGE    200000
#define NLAYER   2

// ---------------- device scratch (no allocs allowed) ----------------
__device__ float g_xs  [N_TOTAL * HIDC];
__device__ float g_K   [N_TOTAL * HIDC];
__device__ float g_Q   [N_TOTAL * HIDC];
__device__ float g_V   [N_TOTAL * HIDC];
__device__ float g_kp  [N_REVIEW * HIDC];
__device__ float g_vp  [N_REVIEW * HIDC];
__device__ float g_outs[N_TOTAL * HIDC];
__device__ float g_gact[N_TOTAL * HIDC];
__device__ float g_ex  [NEDGE * NHEAD];      // logits, then exp values (in place)
__device__ float g_amax[N_REVIEW * NHEAD];   // per (dst,head) max
__device__ float g_den [N_REVIEW * NHEAD];   // per (dst,head) sum

// ---------------- SGEMM: C[M,N] = A[M,K] @ B[K,N] + bias, fused epilogues ----
// EPI 0: bias only ; EPI 1: bias + leaky_relu(0.01) ; EPI 2: bias + sigmoid-skip blend (C in/out)
#define BM 128
#define BN 128
#define BK 16
#define TM 8
#define TN 8

template <int EPI>
__global__ void __launch_bounds__(256)
sgemm_kernel(const float* __restrict__ A, const float* __restrict__ B,
             const float* __restrict__ bias, float* __restrict__ C,
             int M, int N, int K, const float* __restrict__ skip_ptr)
{
    __shared__ float As[BK][BM];
    __shared__ float Bs[BK][BN];

    const int tid = threadIdx.x;
    const int bm  = blockIdx.y * BM;
    const int bn  = blockIdx.x * BN;

    const int aRow = tid >> 2;          // 0..63
    const int aCol = (tid & 3) * 4;     // 0,4,8,12
    const int bRow = tid >> 5;          // 0..7
    const int bCol = (tid & 31) * 4;    // 0..124

    const int tr = (tid >> 4) * TM;     // 0..120
    const int tc = (tid & 15) * TN;     // 0..120

    float acc[TM][TN];
#pragma unroll
    for (int i = 0; i < TM; i++)
#pragma unroll
        for (int j = 0; j < TN; j++) acc[i][j] = 0.f;

    for (int k0 = 0; k0 < K; k0 += BK) {
#pragma unroll
        for (int p = 0; p < 2; p++) {
            int r = aRow + p * 64;
            float4 v = make_float4(0.f, 0.f, 0.f, 0.f);
            if (bm + r < M)
                v = *(const float4*)(A + (size_t)(bm + r) * K + k0 + aCol);
            As[aCol + 0][r] = v.x;
            As[aCol + 1][r] = v.y;
            As[aCol + 2][r] = v.z;
            As[aCol + 3][r] = v.w;
        }
#pragma unroll
        for (int p = 0; p < 2; p++) {
            int r = bRow + p * 8;
            *(float4*)&Bs[r][bCol] =
                *(const float4*)(B + (size_t)(k0 + r) * N + bn + bCol);
        }
        __syncthreads();

#pragma unroll
        for (int k = 0; k < BK; k++) {
            float ra[TM], rb[TN];
#pragma unroll
            for (int i = 0; i < TM; i++) ra[i] = As[k][tr + i];
#pragma unroll
            for (int j = 0; j < TN; j++) rb[j] = Bs[k][tc + j];
#pragma unroll
            for (int i = 0; i < TM; i++)
#pragma unroll
                for (int j = 0; j < TN; j++) acc[i][j] += ra[i] * rb[j];
        }
        __syncthreads();
    }

    float g = 0.f;
    if (EPI == 2) {
        float s = *skip_ptr;
        g = 1.f / (1.f + expf(-s));
    }

#pragma unroll
    for (int i = 0; i < TM; i++) {
        int row = bm + tr + i;
        if (row >= M) continue;
#pragma unroll
        for (int j = 0; j < TN; j++) {
            int col = bn + tc + j;
            float v = acc[i][j] + bias[col];
            if (EPI == 1) v = (v > 0.f) ? v : 0.01f * v;
            if (EPI == 2) {
                float oldv = C[(size_t)row * N + col];
                v = g * v + (1.f - g) * oldv;
            }
            C[(size_t)row * N + col] = v;
        }
    }
}

// ---------------- relation transform: Y[n,h,e] = sum_d X[n,h,d] * A[h,d,e] ----
#define RT_NODES 8
__global__ void __launch_bounds__(256)
rel_transform_kernel(const float* __restrict__ X, const float* __restrict__ A,
                     float* __restrict__ Y, int n)
{
    __shared__ float sA[NHEAD * DHEAD * DHEAD];  // 32 KB
    __shared__ float sX[RT_NODES * HIDC];        // 8 KB

    const int tid = threadIdx.x;
    for (int i = tid; i < NHEAD * DHEAD * DHEAD; i += 256) sA[i] = A[i];

    const int base = blockIdx.x * RT_NODES;
    for (int i = tid; i < RT_NODES * HIDC; i += 256) {
        int node = base + (i >> 8);
        sX[i] = (node < n) ? X[(size_t)node * HIDC + (i & 255)] : 0.f;
    }
    __syncthreads();

    const int h = tid >> 5;
    const int e = tid & 31;
    const float* Ah = sA + h * (DHEAD * DHEAD);

    for (int j = 0; j < RT_NODES; j++) {
        int node = base + j;
        if (node >= n) break;
        const float* xr = sX + j * HIDC + h * DHEAD;
        float accv = 0.f;
#pragma unroll
        for (int d = 0; d < DHEAD; d++) accv += xr[d] * Ah[d * DHEAD + e];
        Y[(size_t)node * HIDC + h * DHEAD + e] = accv;
    }
}

// ---------------- edge kernels ----------------
__device__ __forceinline__ void atomicMaxF(float* addr, float v)
{
    if (v >= 0.f) atomicMax((int*)addr, __float_as_int(v));
    else          atomicMin((unsigned int*)addr, __float_as_uint(v));
}

__global__ void fill_kernel(float* __restrict__ p, float v, int n)
{
    int i = blockIdx.x * blockDim.x + threadIdx.x;
    if (i < n) p[i] = v;
}

// warp per edge: logits + per-(dst,head) atomic max
__global__ void __launch_bounds__(256)
edge_logits_kernel(const float* __restrict__ kp, const float* __restrict__ Q,
                   const int* __restrict__ src, const int* __restrict__ dst,
                   const float* __restrict__ prel,
                   float* __restrict__ logits, float* __restrict__ amax, int nE)
{
    const int gw   = (blockIdx.x * blockDim.x + threadIdx.x) >> 5;
    const int lane = threadIdx.x & 31;
    if (gw >= nE) return;
    const int s = __ldg(src + gw);
    const int d = __ldg(dst + gw);
    const float* kr = kp + (size_t)s * HIDC;
    const float* qr = Q  + (size_t)d * HIDC;
    const float inv_sqrt_d = 0.17677669529663689f;   // 1/sqrt(32)

#pragma unroll
    for (int h = 0; h < NHEAD; h++) {
        float v = kr[h * DHEAD + lane] * qr[h * DHEAD + lane];
#pragma unroll
        for (int o = 16; o > 0; o >>= 1) v += __shfl_xor_sync(0xffffffffu, v, o);
        if (lane == 0) {
            v *= prel[h] * inv_sqrt_d;
            logits[gw * NHEAD + h] = v;
            atomicMaxF(&amax[d * NHEAD + h], v);
        }
    }
}

// thread per (edge,head): exp + denominator accumulation (logits -> ex in place)
__global__ void __launch_bounds__(256)
edge_expsum_kernel(float* __restrict__ logits, const float* __restrict__ amax,
                   float* __restrict__ den, const int* __restrict__ dst, int nE)
{
    int i = blockIdx.x * blockDim.x + threadIdx.x;
    if (i >= nE * NHEAD) return;
    int e = i >> 3, h = i & 7;
    int d = __ldg(dst + e);
    float ex = expf(logits[i] - amax[d * NHEAD + h]);
    logits[i] = ex;
    atomicAdd(&den[d * NHEAD + h], ex);
}

// warp per edge: scatter v * attn into outs via atomics
__global__ void __launch_bounds__(256)
edge_scatter_kernel(const float* __restrict__ vp, const float* __restrict__ ex,
                    const float* __restrict__ den,
                    const int* __restrict__ src, const int* __restrict__ dst,
                    float* __restrict__ outs, int nE)
{
    const int gw   = (blockIdx.x * blockDim.x + threadIdx.x) >> 5;
    const int lane = threadIdx.x & 31;
    if (gw >= nE) return;
    const int s = __ldg(src + gw);
    const int d = __ldg(dst + gw);

#pragma unroll
    for (int h = 0; h < NHEAD; h++) {
        float attn = ex[gw * NHEAD + h] / (den[d * NHEAD + h] + 1e-16f);
        float msg  = vp[(size_t)s * HIDC + h * DHEAD + lane] * attn;
        atomicAdd(&outs[(size_t)d * HIDC + h * DHEAD + lane], msg);
    }
}

// exact gelu
__global__ void gelu_kernel(const float* __restrict__ in, float* __restrict__ out, int n)
{
    int i = blockIdx.x * blockDim.x + threadIdx.x;
    if (i < n) {
        float x = in[i];
        out[i] = 0.5f * x * (1.f + erff(x * 0.7071067811865476f));
    }
}

// ---------------- host-side orchestration ----------------
static inline void launch_gemm(int epi, const float* A, const float* B,
                               const float* bias, float* C, int M, int N, int K,
                               const float* skip_ptr)
{
    dim3 grid(N / BN, (M + BM - 1) / BM);
    dim3 block(256);
    if (epi == 0)      sgemm_kernel<0><<<grid, block>>>(A, B, bias, C, M, N, K, skip_ptr);
    else if (epi == 1) sgemm_kernel<1><<<grid, block>>>(A, B, bias, C, M, N, K, skip_ptr);
    else               sgemm_kernel<2><<<grid, block>>>(A, B, bias, C, M, N, K, skip_ptr);
}

extern "C" void kernel_launch(void* const* d_in, const int* in_sizes, int n_in,
                              void* d_out, int out_size)
{
    const float* x_user   = (const float*)d_in[0];
    const float* x_movie  = (const float*)d_in[1];
    const float* x_review = (const float*)d_in[2];
    const int* src_mr = (const int*)d_in[3];
    const int* dst_mr = (const int*)d_in[4];
    const int* src_ur = (const int*)d_in[5];
    const int* dst_ur = (const int*)d_in[6];
    const int* src_ru = (const int*)d_in[7];
    const int* dst_ru = (const int*)d_in[8];
    const float* W1 = (const float*)d_in[9];
    const float* b1 = (const float*)d_in[10];
    const float* W2 = (const float*)d_in[11];
    const float* b2 = (const float*)d_in[12];
    const float* Wk = (const float*)d_in[13];
    const float* bk = (const float*)d_in[14];
    const float* Wq = (const float*)d_in[15];
    const float* bq = (const float*)d_in[16];
    const float* Wv = (const float*)d_in[17];
    const float* bv = (const float*)d_in[18];
    const float* Wa = (const float*)d_in[19];
    const float* ba = (const float*)d_in[20];
    const float* skip  = (const float*)d_in[21];
    const float* a_rel = (const float*)d_in[22];
    const float* m_rel = (const float*)d_in[23];
    const float* p_rel = (const float*)d_in[24];

    float *xs, *Kb, *Qb, *Vb, *kp, *vp, *outs, *gact, *exb, *amax, *den;
    cudaGetSymbolAddress((void**)&xs,   g_xs);
    cudaGetSymbolAddress((void**)&Kb,   g_K);
    cudaGetSymbolAddress((void**)&Qb,   g_Q);
    cudaGetSymbolAddress((void**)&Vb,   g_V);
    cudaGetSymbolAddress((void**)&kp,   g_kp);
    cudaGetSymbolAddress((void**)&vp,   g_vp);
    cudaGetSymbolAddress((void**)&outs, g_outs);
    cudaGetSymbolAddress((void**)&gact, g_gact);
    cudaGetSymbolAddress((void**)&exb,  g_ex);
    cudaGetSymbolAddress((void**)&amax, g_amax);
    cudaGetSymbolAddress((void**)&den,  g_den);

    const int off[3] = {0, N_USER, N_USER + N_MOVIE};
    const int cnt[3] = {N_USER, N_MOVIE, N_REVIEW};
    const float* xin[3] = {x_user, x_movie, x_review};

    // edge types: (src_type, dst_type, src_idx, dst_idx)
    const int   e_s[3]  = {1, 0, 2};
    const int   e_t[3]  = {2, 2, 0};
    const int* e_src[3] = {src_mr, src_ur, src_ru};
    const int* e_dst[3] = {dst_mr, dst_ur, dst_ru};

    // ---- input MLP: xs = lrelu(x @ W1 + b1) ----
    for (int t = 0; t < 3; t++)
        launch_gemm(1, xin[t], W1, b1, xs + (size_t)off[t] * HIDC,
                    cnt[t], HIDC, IN_CH, nullptr);

    const int edge_warp_blocks = (NEDGE * 32 + 255) / 256;
    const int edge_eh_blocks   = (NEDGE * NHEAD + 255) / 256;

    for (int l = 0; l < NLAYER; l++) {
        // ---- K/Q/V projections per node type ----
        for (int t = 0; t < 3; t++) {
            size_t wo = (size_t)(l * 3 + t) * HIDC * HIDC;
            size_t bo = (size_t)(l * 3 + t) * HIDC;
            launch_gemm(0, xs + (size_t)off[t] * HIDC, Wk + wo, bk + bo,
                        Kb + (size_t)off[t] * HIDC, cnt[t], HIDC, HIDC, nullptr);
            launch_gemm(0, xs + (size_t)off[t] * HIDC, Wq + wo, bq + bo,
                        Qb + (size_t)off[t] * HIDC, cnt[t], HIDC, HIDC, nullptr);
            launch_gemm(0, xs + (size_t)off[t] * HIDC, Wv + wo, bv + bo,
                        Vb + (size_t)off[t] * HIDC, cnt[t], HIDC, HIDC, nullptr);
        }

        cudaMemsetAsync(outs, 0, (size_t)N_TOTAL * HIDC * sizeof(float));

        // ---- message passing per edge type ----
        for (int e = 0; e < 3; e++) {
            int s = e_s[e], t = e_t[e];
            int ns = cnt[s], nt = cnt[t];
            size_t relo = (size_t)(l * 3 + e) * NHEAD * DHEAD * DHEAD;

            rel_transform_kernel<<<(ns + RT_NODES - 1) / RT_NODES, 256>>>(
                Kb + (size_t)off[s] * HIDC, a_rel + relo, kp, ns);
            rel_transform_kernel<<<(ns + RT_NODES - 1) / RT_NODES, 256>>>(
                Vb + (size_t)off[s] * HIDC, m_rel + relo, vp, ns);

            fill_kernel<<<(nt * NHEAD + 255) / 256, 256>>>(
                amax, -INFINITY, nt * NHEAD);
            cudaMemsetAsync(den, 0, (size_t)nt * NHEAD * sizeof(float));

            edge_logits_kernel<<<edge_warp_blocks, 256>>>(
                kp, Qb + (size_t)off[t] * HIDC, e_src[e], e_dst[e],
                p_rel + (size_t)(l * 3 + e) * NHEAD, exb, amax, NEDGE);
            edge_expsum_kernel<<<edge_eh_blocks, 256>>>(
                exb, amax, den, e_dst[e], NEDGE);
            edge_scatter_kernel<<<edge_warp_blocks, 256>>>(
                vp, exb, den, e_src[e], e_dst[e],
                outs + (size_t)off[t] * HIDC, NEDGE);
        }

        // ---- gelu + output projection + skip blend ----
        gelu_kernel<<<(N_TOTAL * HIDC + 255) / 256, 256>>>(outs, gact, N_TOTAL * HIDC);
        for (int t = 0; t < 3; t++) {
            size_t wo = (size_t)(l * 3 + t) * HIDC * HIDC;
            size_t bo = (size_t)(l * 3 + t) * HIDC;
            launch_gemm(2, gact + (size_t)off[t] * HIDC, Wa + wo, ba + bo,
                        xs + (size_t)off[t] * HIDC, cnt[t], HIDC, HIDC,
                        skip + l * 3 + t);
        }
    }

    // ---- output MLP: out = lrelu(xs @ W2 + b2), concat order already matches ----
    launch_gemm(1, xs, W2, b2, (float*)d_out, N_TOTAL, OUT_CH, HIDC, nullptr);
}

// round 4
// speedup vs baseline: 3.0107x; 3.0107x over previous
#include <cuda_runtime.h>
#include <math.h>
#include <stdint.h>

// ---------------- problem constants ----------------
#define N_USER   50000
#define N_MOVIE  20000
#define N_REVIEW 200000
#define N_TOTAL  270000
#define IN_CH    768
#define HIDC     256
#define OUT_CH   128
#define NHEAD    8
#define DHEAD    32
#define NEDGE    200000
#define NLAYER   2

// ---------------- device scratch (no allocs allowed) ----------------
__device__ float g_xs   [N_TOTAL * HIDC];
__device__ float g_Q    [N_TOTAL * HIDC];
__device__ float g_kp   [N_TOTAL * HIDC];
__device__ float g_vp   [N_TOTAL * HIDC];
__device__ float g_outs [N_TOTAL * HIDC];
__device__ float g_gact [N_TOTAL * HIDC];
__device__ float g_ex   [NEDGE * NHEAD];
__device__ float g_amax [N_REVIEW * NHEAD];
__device__ float g_den  [N_REVIEW * NHEAD];
__device__ float g_Wfold[12 * HIDC * HIDC];   // folded K/V weights per (layer,edge,{k,v})
__device__ float g_bfold[12 * HIDC];

// ================= tf32 tensor-core GEMM =================
// C[M,N] = A[M,K] @ B[K,N] (+bias, epilogue). BM=BN=128, BK=32, 256 thr (8 warps, 4x2),
// warp tile 32x64 via mma.sync.m16n8k8 tf32. cp.async double buffer.
#define BM 128
#define BN 128
#define BK 32
#define APAD 4
#define BPAD 8
#define ASTRIDE (BK + APAD)          // 36 floats
#define BSTRIDE (BN + BPAD)          // 136 floats
#define A_STAGE (BM * ASTRIDE)       // 4608 floats
#define B_STAGE (BK * BSTRIDE)       // 4352 floats
#define SMEM_FLOATS (2 * A_STAGE + 2 * B_STAGE)
#define SMEM_BYTES  (SMEM_FLOATS * 4)   // 71680

__device__ __forceinline__ unsigned cvt_tf32(float x)
{
    unsigned u;
    asm("cvt.rna.tf32.f32 %0, %1;" : "=r"(u) : "f"(x));
    return u;
}

__device__ __forceinline__ void cp_async16(uint32_t saddr, const void* g, int sz)
{
    asm volatile("cp.async.cg.shared.global [%0], [%1], 16, %2;\n"
                 :: "r"(saddr), "l"(g), "r"(sz));
}

__device__ __forceinline__ void mma_tf32(float& c0, float& c1, float& c2, float& c3,
                                         unsigned a0, unsigned a1, unsigned a2, unsigned a3,
                                         unsigned b0, unsigned b1)
{
    asm volatile(
        "mma.sync.aligned.m16n8k8.row.col.f32.tf32.tf32.f32 "
        "{%0,%1,%2,%3}, {%4,%5,%6,%7}, {%8,%9}, {%0,%1,%2,%3};\n"
        : "+f"(c0), "+f"(c1), "+f"(c2), "+f"(c3)
        : "r"(a0), "r"(a1), "r"(a2), "r"(a3), "r"(b0), "r"(b1));
}

// EPI 0: bias ; 1: bias + leaky_relu(0.01) ; 2: bias + sigmoid-skip blend (C in/out)
template <int EPI>
__global__ void __launch_bounds__(256, 2)
tgemm_kernel(const float* __restrict__ A, const float* __restrict__ B,
             const float* __restrict__ bias, float* __restrict__ C,
             int M, int N, int K, const float* __restrict__ skip_ptr)
{
    extern __shared__ float sm[];
    float* sA = sm;
    float* sB = sm + 2 * A_STAGE;

    const int tid = threadIdx.x;
    const int bm = blockIdx.y * BM;
    const int bn = blockIdx.x * BN;

    const int warp = tid >> 5, lane = tid & 31;
    const int wr = warp & 3, wc = warp >> 2;   // warp row 0..3 (x32), col 0..1 (x64)
    const int g  = lane >> 2, tg = lane & 3;

    const int mbase = wr * 32;
    const int nbase = wc * 64;

    float c[2][8][4];
#pragma unroll
    for (int mt = 0; mt < 2; mt++)
#pragma unroll
        for (int nt = 0; nt < 8; nt++)
#pragma unroll
            for (int i = 0; i < 4; i++) c[mt][nt][i] = 0.f;

    uint32_t saA = (uint32_t)__cvta_generic_to_shared(sA);
    uint32_t saB = (uint32_t)__cvta_generic_to_shared(sB);

    const int KT = K / BK;

    auto load_tile = [&](int kt, int stage) {
        const int k0 = kt * BK;
#pragma unroll
        for (int i = 0; i < 4; i++) {
            int ch  = tid + i * 256;               // 0..1023
            int row = ch >> 3;
            int kc  = (ch & 7) * 4;
            bool p  = (bm + row) < M;
            int rr  = p ? (bm + row) : 0;
            uint32_t da = saA + (uint32_t)((stage * A_STAGE + row * ASTRIDE + kc) * 4);
            cp_async16(da, A + (size_t)rr * K + k0 + kc, p ? 16 : 0);
        }
#pragma unroll
        for (int i = 0; i < 4; i++) {
            int ch = tid + i * 256;
            int kr = ch >> 5;
            int nc = (ch & 31) * 4;
            uint32_t db = saB + (uint32_t)((stage * B_STAGE + kr * BSTRIDE + nc) * 4);
            cp_async16(db, B + (size_t)(k0 + kr) * N + bn + nc, 16);
        }
        asm volatile("cp.async.commit_group;\n");
    };

    load_tile(0, 0);

    for (int kt = 0; kt < KT; kt++) {
        if (kt + 1 < KT) {
            load_tile(kt + 1, (kt + 1) & 1);
            asm volatile("cp.async.wait_group 1;\n");
        } else {
            asm volatile("cp.async.wait_group 0;\n");
        }
        __syncthreads();

        const float* tA = sA + (kt & 1) * A_STAGE;
        const float* tB = sB + (kt & 1) * B_STAGE;

#pragma unroll
        for (int kk = 0; kk < BK / 8; kk++) {
            unsigned af[2][4];
#pragma unroll
            for (int mt = 0; mt < 2; mt++) {
                int r0 = mbase + mt * 16 + g;
                const float* pr0 = tA + r0 * ASTRIDE + kk * 8 + tg;
                const float* pr1 = tA + (r0 + 8) * ASTRIDE + kk * 8 + tg;
                af[mt][0] = cvt_tf32(pr0[0]);
                af[mt][1] = cvt_tf32(pr1[0]);
                af[mt][2] = cvt_tf32(pr0[4]);
                af[mt][3] = cvt_tf32(pr1[4]);
            }
            unsigned bf[8][2];
#pragma unroll
            for (int nt = 0; nt < 8; nt++) {
                int col = nbase + nt * 8 + g;
                bf[nt][0] = cvt_tf32(tB[(kk * 8 + tg) * BSTRIDE + col]);
                bf[nt][1] = cvt_tf32(tB[(kk * 8 + tg + 4) * BSTRIDE + col]);
            }
#pragma unroll
            for (int mt = 0; mt < 2; mt++)
#pragma unroll
                for (int nt = 0; nt < 8; nt++)
                    mma_tf32(c[mt][nt][0], c[mt][nt][1], c[mt][nt][2], c[mt][nt][3],
                             af[mt][0], af[mt][1], af[mt][2], af[mt][3],
                             bf[nt][0], bf[nt][1]);
        }
        __syncthreads();
    }

    float gmix = 0.f;
    if (EPI == 2) {
        float s = *skip_ptr;
        gmix = 1.f / (1.f + expf(-s));
    }

#pragma unroll
    for (int mt = 0; mt < 2; mt++) {
        int r0 = bm + mbase + mt * 16 + g;
        int r1 = r0 + 8;
#pragma unroll
        for (int nt = 0; nt < 8; nt++) {
            int col = bn + nbase + nt * 8 + tg * 2;
            float bx = bias[col], by = bias[col + 1];
            if (r0 < M) {
                float vx = c[mt][nt][0] + bx;
                float vy = c[mt][nt][1] + by;
                if (EPI == 1) { vx = vx > 0.f ? vx : 0.01f * vx; vy = vy > 0.f ? vy : 0.01f * vy; }
                if (EPI == 2) {
                    float2 old = *(const float2*)(C + (size_t)r0 * N + col);
                    vx = gmix * vx + (1.f - gmix) * old.x;
                    vy = gmix * vy + (1.f - gmix) * old.y;
                }
                float2 o; o.x = vx; o.y = vy;
                *(float2*)(C + (size_t)r0 * N + col) = o;
            }
            if (r1 < M) {
                float vx = c[mt][nt][2] + bx;
                float vy = c[mt][nt][3] + by;
                if (EPI == 1) { vx = vx > 0.f ? vx : 0.01f * vx; vy = vy > 0.f ? vy : 0.01f * vy; }
                if (EPI == 2) {
                    float2 old = *(const float2*)(C + (size_t)r1 * N + col);
                    vx = gmix * vx + (1.f - gmix) * old.x;
                    vy = gmix * vy + (1.f - gmix) * old.y;
                }
                float2 o; o.x = vx; o.y = vy;
                *(float2*)(C + (size_t)r1 * N + col) = o;
            }
        }
    }
}

// ================ weight folding ================
// We[i, h*32+e] = scale(h) * sum_d W[i, h*32+d] * R[h,d,e] ; row 256 folds bias.
// scale = p_rel[h]/sqrt(D) for K-folds, 1 for V-folds (prel == nullptr).
__global__ void __launch_bounds__(256)
fold_kernel(const float* __restrict__ W, const float* __restrict__ b,
            const float* __restrict__ R, const float* __restrict__ prel,
            float* __restrict__ We, float* __restrict__ be)
{
    const int row = blockIdx.x;           // 0..256 (256 == bias)
    const int tid = threadIdx.x;          // h*32+e
    const int h = tid >> 5, e = tid & 31;
    const float* src = (row < HIDC) ? (W + (size_t)row * HIDC) : b;
    const float* Rh = R + h * (DHEAD * DHEAD);
    float acc = 0.f;
#pragma unroll 8
    for (int d = 0; d < DHEAD; d++)
        acc += src[h * DHEAD + d] * Rh[d * DHEAD + e];
    if (prel) acc *= prel[h] * 0.17677669529663689f;  // 1/sqrt(32)
    if (row < HIDC) We[(size_t)row * HIDC + tid] = acc;
    else            be[tid] = acc;
}

// ================ edge kernels ================
__device__ __forceinline__ void atomicMaxF(float* addr, float v)
{
    if (v >= 0.f) atomicMax((int*)addr, __float_as_int(v));
    else          atomicMin((unsigned int*)addr, __float_as_uint(v));
}

__global__ void fill_kernel(float* __restrict__ p, float v, int n)
{
    int i = blockIdx.x * blockDim.x + threadIdx.x;
    if (i < n) p[i] = v;
}

// warp per edge: logits (prel/scale pre-folded into kp) + per-(dst,head) atomic max
__global__ void __launch_bounds__(256)
edge_logits_kernel(const float* __restrict__ kp, const float* __restrict__ Q,
                   const int* __restrict__ src, const int* __restrict__ dst,
                   float* __restrict__ logits, float* __restrict__ amax, int nE)
{
    const int gw   = (blockIdx.x * blockDim.x + threadIdx.x) >> 5;
    const int lane = threadIdx.x & 31;
    if (gw >= nE) return;
    const int s = __ldg(src + gw);
    const int d = __ldg(dst + gw);
    const float* kr = kp + (size_t)s * HIDC;
    const float* qr = Q  + (size_t)d * HIDC;

#pragma unroll
    for (int h = 0; h < NHEAD; h++) {
        float v = kr[h * DHEAD + lane] * qr[h * DHEAD + lane];
#pragma unroll
        for (int o = 16; o > 0; o >>= 1) v += __shfl_xor_sync(0xffffffffu, v, o);
        if (lane == 0) {
            logits[gw * NHEAD + h] = v;
            atomicMaxF(&amax[d * NHEAD + h], v);
        }
    }
}

__global__ void __launch_bounds__(256)
edge_expsum_kernel(float* __restrict__ logits, const float* __restrict__ amax,
                   float* __restrict__ den, const int* __restrict__ dst, int nE)
{
    int i = blockIdx.x * blockDim.x + threadIdx.x;
    if (i >= nE * NHEAD) return;
    int e = i >> 3, h = i & 7;
    int d = __ldg(dst + e);
    float ex = expf(logits[i] - amax[d * NHEAD + h]);
    logits[i] = ex;
    atomicAdd(&den[d * NHEAD + h], ex);
}

__global__ void __launch_bounds__(256)
edge_scatter_kernel(const float* __restrict__ vp, const float* __restrict__ ex,
                    const float* __restrict__ den,
                    const int* __restrict__ src, const int* __restrict__ dst,
                    float* __restrict__ outs, int nE)
{
    const int gw   = (blockIdx.x * blockDim.x + threadIdx.x) >> 5;
    const int lane = threadIdx.x & 31;
    if (gw >= nE) return;
    const int s = __ldg(src + gw);
    const int d = __ldg(dst + gw);

#pragma unroll
    for (int h = 0; h < NHEAD; h++) {
        float attn = ex[gw * NHEAD + h] / (den[d * NHEAD + h] + 1e-16f);
        float msg  = vp[(size_t)s * HIDC + h * DHEAD + lane] * attn;
        atomicAdd(&outs[(size_t)d * HIDC + h * DHEAD + lane], msg);
    }
}

__global__ void gelu_kernel(const float* __restrict__ in, float* __restrict__ out, int n)
{
    int i = blockIdx.x * blockDim.x + threadIdx.x;
    if (i < n) {
        float x = in[i];
        out[i] = 0.5f * x * (1.f + erff(x * 0.7071067811865476f));
    }
}

// movie nodes receive no edges: new_x = g*ba + (1-g)*x
__global__ void movie_blend_kernel(float* __restrict__ xs_movie,
                                   const float* __restrict__ ba,
                                   const float* __restrict__ skip_ptr, int n)
{
    int i = blockIdx.x * blockDim.x + threadIdx.x;
    if (i >= n) return;
    float gmix = 1.f / (1.f + expf(-*skip_ptr));
    float old = xs_movie[i];
    xs_movie[i] = gmix * ba[i & (HIDC - 1)] + (1.f - gmix) * old;
}

// ---------------- host-side orchestration ----------------
static inline void launch_tgemm(int epi, const float* A, const float* B,
                                const float* bias, float* C, int M, int N, int K,
                                const float* skip_ptr)
{
    dim3 grid(N / BN, (M + BM - 1) / BM);
    if (epi == 0)      tgemm_kernel<0><<<grid, 256, SMEM_BYTES>>>(A, B, bias, C, M, N, K, skip_ptr);
    else if (epi == 1) tgemm_kernel<1><<<grid, 256, SMEM_BYTES>>>(A, B, bias, C, M, N, K, skip_ptr);
    else               tgemm_kernel<2><<<grid, 256, SMEM_BYTES>>>(A, B, bias, C, M, N, K, skip_ptr);
}

extern "C" void kernel_launch(void* const* d_in, const int* in_sizes, int n_in,
                              void* d_out, int out_size)
{
    const float* x_user   = (const float*)d_in[0];
    const float* x_movie  = (const float*)d_in[1];
    const float* x_review = (const float*)d_in[2];
    const int* src_mr = (const int*)d_in[3];
    const int* dst_mr = (const int*)d_in[4];
    const int* src_ur = (const int*)d_in[5];
    const int* dst_ur = (const int*)d_in[6];
    const int* src_ru = (const int*)d_in[7];
    const int* dst_ru = (const int*)d_in[8];
    const float* W1 = (const float*)d_in[9];
    const float* b1 = (const float*)d_in[10];
    const float* W2 = (const float*)d_in[11];
    const float* b2 = (const float*)d_in[12];
    const float* Wk = (const float*)d_in[13];
    const float* bk = (const float*)d_in[14];
    const float* Wq = (const float*)d_in[15];
    const float* bq = (const float*)d_in[16];
    const float* Wv = (const float*)d_in[17];
    const float* bv = (const float*)d_in[18];
    const float* Wa = (const float*)d_in[19];
    const float* ba = (const float*)d_in[20];
    const float* skip  = (const float*)d_in[21];
    const float* a_rel = (const float*)d_in[22];
    const float* m_rel = (const float*)d_in[23];
    const float* p_rel = (const float*)d_in[24];

    cudaFuncSetAttribute(tgemm_kernel<0>, cudaFuncAttributeMaxDynamicSharedMemorySize, SMEM_BYTES);
    cudaFuncSetAttribute(tgemm_kernel<1>, cudaFuncAttributeMaxDynamicSharedMemorySize, SMEM_BYTES);
    cudaFuncSetAttribute(tgemm_kernel<2>, cudaFuncAttributeMaxDynamicSharedMemorySize, SMEM_BYTES);

    float *xs, *Qb, *kp, *vp, *outs, *gact, *exb, *amax, *den, *Wfold, *bfold;
    cudaGetSymbolAddress((void**)&xs,    g_xs);
    cudaGetSymbolAddress((void**)&Qb,    g_Q);
    cudaGetSymbolAddress((void**)&kp,    g_kp);
    cudaGetSymbolAddress((void**)&vp,    g_vp);
    cudaGetSymbolAddress((void**)&outs,  g_outs);
    cudaGetSymbolAddress((void**)&gact,  g_gact);
    cudaGetSymbolAddress((void**)&exb,   g_ex);
    cudaGetSymbolAddress((void**)&amax,  g_amax);
    cudaGetSymbolAddress((void**)&den,   g_den);
    cudaGetSymbolAddress((void**)&Wfold, g_Wfold);
    cudaGetSymbolAddress((void**)&bfold, g_bfold);

    const int off[3] = {0, N_USER, N_USER + N_MOVIE};          // node-type offsets
    const int cnt[3] = {N_USER, N_MOVIE, N_REVIEW};
    const float* xin[3] = {x_user, x_movie, x_review};

    // edge types: (src_type, dst_type)
    const int   e_s[3]  = {1, 0, 2};
    const int   e_t[3]  = {2, 2, 0};
    const int* e_src[3] = {src_mr, src_ur, src_ru};
    const int* e_dst[3] = {dst_mr, dst_ur, dst_ru};
    const int  segoff[3] = {0, N_MOVIE, N_MOVIE + N_USER};     // kp/vp segment per edge type

    // ---- fold all relation matrices into K/V weights (tiny) ----
    for (int l = 0; l < NLAYER; l++)
        for (int e = 0; e < 3; e++) {
            int s = e_s[e];
            size_t wsrc = (size_t)(l * 3 + s) * HIDC * HIDC;
            size_t bsrc = (size_t)(l * 3 + s) * HIDC;
            size_t rsrc = (size_t)(l * 3 + e) * NHEAD * DHEAD * DHEAD;
            int fk = ((l * 3 + e) * 2 + 0), fv = ((l * 3 + e) * 2 + 1);
            fold_kernel<<<HIDC + 1, 256>>>(Wk + wsrc, bk + bsrc, a_rel + rsrc,
                                           p_rel + (size_t)(l * 3 + e) * NHEAD,
                                           Wfold + (size_t)fk * HIDC * HIDC,
                                           bfold + (size_t)fk * HIDC);
            fold_kernel<<<HIDC + 1, 256>>>(Wv + wsrc, bv + bsrc, m_rel + rsrc,
                                           nullptr,
                                           Wfold + (size_t)fv * HIDC * HIDC,
                                           bfold + (size_t)fv * HIDC);
        }

    // ---- input MLP ----
    for (int t = 0; t < 3; t++)
        launch_tgemm(1, xin[t], W1, b1, xs + (size_t)off[t] * HIDC,
                     cnt[t], HIDC, IN_CH, nullptr);

    const int edge_warp_blocks = (NEDGE * 32 + 255) / 256;
    const int edge_eh_blocks   = (NEDGE * NHEAD + 255) / 256;

    for (int l = 0; l < NLAYER; l++) {
        // Q only for receiving node types (user=0, review=2)
        for (int tt = 0; tt < 2; tt++) {
            int t = (tt == 0) ? 0 : 2;
            size_t wo = (size_t)(l * 3 + t) * HIDC * HIDC;
            size_t bo = (size_t)(l * 3 + t) * HIDC;
            launch_tgemm(0, xs + (size_t)off[t] * HIDC, Wq + wo, bq + bo,
                         Qb + (size_t)off[t] * HIDC, cnt[t], HIDC, HIDC, nullptr);
        }
        // folded kp/vp per edge type (relation transform fused into the GEMM)
        for (int e = 0; e < 3; e++) {
            int s = e_s[e];
            int fk = ((l * 3 + e) * 2 + 0), fv = ((l * 3 + e) * 2 + 1);
            launch_tgemm(0, xs + (size_t)off[s] * HIDC,
                         Wfold + (size_t)fk * HIDC * HIDC, bfold + (size_t)fk * HIDC,
                         kp + (size_t)segoff[e] * HIDC, cnt[s], HIDC, HIDC, nullptr);
            launch_tgemm(0, xs + (size_t)off[s] * HIDC,
                         Wfold + (size_t)fv * HIDC * HIDC, bfold + (size_t)fv * HIDC,
                         vp + (size_t)segoff[e] * HIDC, cnt[s], HIDC, HIDC, nullptr);
        }

        cudaMemsetAsync(outs, 0, (size_t)N_TOTAL * HIDC * sizeof(float));

        for (int e = 0; e < 3; e++) {
            int t = e_t[e];
            int nt = cnt[t];
            fill_kernel<<<(nt * NHEAD + 255) / 256, 256>>>(amax, -INFINITY, nt * NHEAD);
            cudaMemsetAsync(den, 0, (size_t)nt * NHEAD * sizeof(float));

            edge_logits_kernel<<<edge_warp_blocks, 256>>>(
                kp + (size_t)segoff[e] * HIDC, Qb + (size_t)off[t] * HIDC,
                e_src[e], e_dst[e], exb, amax, NEDGE);
            edge_expsum_kernel<<<edge_eh_blocks, 256>>>(
                exb, amax, den, e_dst[e], NEDGE);
            edge_scatter_kernel<<<edge_warp_blocks, 256>>>(
                vp + (size_t)segoff[e] * HIDC, exb, den, e_src[e], e_dst[e],
                outs + (size_t)off[t] * HIDC, NEDGE);
        }

        // gelu + Wa (+skip) for user/review; movie is a pure blend with ba
        gelu_kernel<<<(N_TOTAL * HIDC + 255) / 256, 256>>>(outs, gact, N_TOTAL * HIDC);
        for (int tt = 0; tt < 2; tt++) {
            int t = (tt == 0) ? 0 : 2;
            size_t wo = (size_t)(l * 3 + t) * HIDC * HIDC;
            size_t bo = (size_t)(l * 3 + t) * HIDC;
            launch_tgemm(2, gact + (size_t)off[t] * HIDC, Wa + wo, ba + bo,
                         xs + (size_t)off[t] * HIDC, cnt[t], HIDC, HIDC,
                         skip + l * 3 + t);
        }
        movie_blend_kernel<<<(N_MOVIE * HIDC + 255) / 256, 256>>>(
            xs + (size_t)off[1] * HIDC, ba + (size_t)(l * 3 + 1) * HIDC,
            skip + l * 3 + 1, N_MOVIE * HIDC);
    }

    // ---- output MLP ----
    launch_tgemm(1, xs, W2, b2, (float*)d_out, N_TOTAL, OUT_CH, HIDC, nullptr);
}